// round 14
// baseline (speedup 1.0000x reference)
#include <cuda_runtime.h>
#include <math.h>

// Problem constants
constexpr int BB   = 8;
constexpr int NCLS = 2;
constexpr int NSP  = 8;
constexpr int CH   = 64;
constexpr int HH   = 192;
constexpr int WW   = 192;
constexpr int HWSZ = HH * WW;   // 36864
constexpr int RPS  = 6;         // rows per strip in k_P (32 strips now)

// k_P smem layout constants (x stored as duplicated f32x2 pairs)
constexpr int XCHUNK = 102;
constexpr int XSLOT  = 4 * XCHUNK;         // 408
constexpr int XCP    = 3 * XSLOT;          // 1224
constexpr int SPCOLSTRIDE = 18;
constexpr int SPSZ = 3464;

constexpr int LUTN = 512;

typedef unsigned long long u64t;

// ---------------- device scratch ----------------
__device__ float g_space[BB * NCLS * NSP * HWSZ];   // [b][sc][hw]
__device__ float g_S[BB * NCLS * NSP];
__device__ float g_P[BB * NSP * NCLS * CH * 9];     // [b][s][c][c'][k]
__device__ float g_tok[BB * NCLS * CH];             // [b][c][d]
__device__ float g_wT[CH * CH * 9];                 // [d][k][o]
__device__ float g_U[BB * NCLS * 9 * CH];           // [b][c][k][o]
__device__ float g_g[BB * NCLS * HWSZ];             // [b][c][hw]
__device__ float g_lut[LUTN + 2];                   // g(cp) lookup
__device__ float g_bnsum[CH];
__device__ float g_bnsq[CH];

__device__ __forceinline__ float sigmoidf_(float x) {
    return 1.0f / (1.0f + __expf(-x));
}

// ---- packed f32x2 helpers ----
__device__ __forceinline__ u64t pack1(float v) {
    u64t r; asm("mov.b64 %0, {%1, %1};" : "=l"(r) : "f"(v)); return r;
}
__device__ __forceinline__ u64t ffma2(u64t a, u64t b, u64t c) {
    u64t d; asm("fma.rn.f32x2 %0, %1, %2, %3;" : "=l"(d) : "l"(a), "l"(b), "l"(c)); return d;
}
__device__ __forceinline__ float2 unpack2(u64t v) {
    float2 f; asm("mov.b64 {%0, %1}, %2;" : "=f"(f.x), "=f"(f.y) : "l"(v)); return f;
}
// (hi(a), lo(b)) -> new pair
__device__ __forceinline__ u64t shl_pair(u64t a, u64t b) {
    float2 fa = unpack2(a), fb = unpack2(b);
    u64t r; asm("mov.b64 %0, {%1, %2};" : "=l"(r) : "f"(fa.y), "f"(fb.x));
    return r;
}

// ---------------- kernel 0a: zero accumulators + build g-LUT ----------------
__global__ void k_zero(const float* __restrict__ Wcv,
                       const float* __restrict__ Wa,
                       const float* __restrict__ Wcomb) {
    int i = blockIdx.x * blockDim.x + threadIdx.x;
    if (i < BB * NSP * NCLS * CH * 9) g_P[i] = 0.f;
    if (i < CH) { g_bnsum[i] = 0.f; g_bnsq[i] = 0.f; }
    if (i < BB * NCLS * NSP) g_S[i] = 0.f;
    if (i < BB * NCLS * CH) g_tok[i] = 0.f;
    if (i < LUTN + 2) {
        float t = fminf((float)i / (float)LUTN, 1.0f);
        float acc = 0.f;
#pragma unroll
        for (int s = 0; s < 8; s++)
            acc += Wcomb[s] * Wcv[s] * sigmoidf_(Wa[s] * t);
        g_lut[i] = acc;
    }
}

// ---------------- kernel 0b: transpose W_single (OIHW -> [d][k][o]) ----------------
__global__ void k_wT(const float* __restrict__ Ws) {
    int i = blockIdx.x * blockDim.x + threadIdx.x;
    if (i < CH * CH * 9) {
        int o = i / 576;
        int rem = i % 576;
        int d = rem / 9;
        int k = rem % 9;
        g_wT[d * 576 + k * 64 + o] = Ws[i];
    }
}

// ---------------- kernel 1: space channels + sums + g maps (LUT for g) ----------------
// grid (48, 8): 4-row tiles. block 256, 3 pixels/thread.
__global__ __launch_bounds__(256) void k_spaceg(const float* __restrict__ cs,
                                                const float* __restrict__ Wcsp) {
    __shared__ float s_sig[2][6][194];   // sigmoid(cs) tile with halo
    __shared__ float s_lut[LUTN + 2];
    int tid = threadIdx.x;
    int b = blockIdx.y;
    int r0 = blockIdx.x * 4;

    for (int i = tid; i < LUTN + 2; i += 256) s_lut[i] = g_lut[i];

    // load sigmoid tile: 2 classes x 6 rows x 194 cols
    for (int i = tid; i < 2 * 6 * 194; i += 256) {
        int c = i / 1164;
        int rem = i - c * 1164;
        int rr = rem / 194;
        int cc = rem - rr * 194;
        int gh = r0 + rr - 1, gw = cc - 1;
        float v = 0.f;
        if (gh >= 0 && gh < HH && gw >= 0 && gw < WW)
            v = sigmoidf_(cs[(b * NCLS + c) * HWSZ + gh * WW + gw]);
        s_sig[c][rr][cc] = v;
    }
    __syncthreads();

    float sums[2 * NSP];
#pragma unroll
    for (int i = 0; i < 16; i++) sums[i] = 0.f;

#pragma unroll
    for (int pi = 0; pi < 3; pi++) {
        int pl = tid + pi * 256;           // 0..767
        int lr = pl / WW, w = pl - lr * WW;
        int p = (r0 + lr) * WW + w;
#pragma unroll
        for (int c = 0; c < 2; c++) {
            float n[9];
#pragma unroll
            for (int dy = 0; dy < 3; dy++)
#pragma unroll
                for (int dx = 0; dx < 3; dx++)
                    n[dy * 3 + dx] = s_sig[c][lr + dy][w + dx];

            float ch0 = n[4];
            g_space[((b * NCLS + c) * NSP + 0) * HWSZ + p] = ch0;
            sums[c * NSP] += ch0;
#pragma unroll
            for (int j = 0; j < 7; j++) {
                float z = 0.f;
#pragma unroll
                for (int k = 0; k < 9; k++) z += Wcsp[j * 9 + k] * n[k];
                float v = sigmoidf_(z);
                g_space[((b * NCLS + c) * NSP + j + 1) * HWSZ + p] = v;
                sums[c * NSP + j + 1] += v;
            }
            // g via LUT lerp
            float f = ch0 * (float)LUTN;
            int idx = (int)f;
            float fr = f - (float)idx;
            float l0 = s_lut[idx];
            g_g[(b * NCLS + c) * HWSZ + p] = l0 + fr * (s_lut[idx + 1] - l0);
        }
    }

#pragma unroll
    for (int sc = 0; sc < 16; sc++) {
        float v = sums[sc];
#pragma unroll
        for (int off = 16; off; off >>= 1)
            v += __shfl_down_sync(0xffffffffu, v, off);
        if ((tid & 31) == 0) {
            int c = sc / NSP, s = sc % NSP;
            atomicAdd(&g_S[(b * NCLS + c) * NSP + s], v);
        }
    }
}

// ---------------- kernel 2: P correlation (dup-x f32x2, conflict-free) ----------------
__device__ __forceinline__ void load_x_dup(float* s_x, const float* __restrict__ xb,
                                           int grow, int tid) {
    int slot = ((grow % 3) + 3) % 3;
    bool rok = (grow >= 0 && grow < HH);
    const float* rowp = xb + grow * WW;
#pragma unroll
    for (int m = 0; m < 13; m++) {
        int i = tid + m * 128;
        if (i < 1600) {
            int cp = i / 200;
            int rem = i - cp * 200;
            int j = rem / 50;
            int t = rem - j * 50;
            int col = 48 * j - 1 + t;
            float v = 0.f;
            if (rok && col >= 0 && col < WW) v = rowp[cp * HWSZ + col];
            *(u64t*)(s_x + cp * XCP + slot * XSLOT + j * XCHUNK + 2 * t) = pack1(v);
        }
    }
}

__global__ __launch_bounds__(128) void k_P(const float* __restrict__ x) {
    __shared__ __align__(16) float s_x[8 * XCP];      // 39.2 KB
    __shared__ __align__(16) float s_spT[SPSZ];       // 13.9 KB

    int b = blockIdx.z, cgrp = blockIdx.y, strip = blockIdx.x;
    int r0 = strip * RPS;
    int tid = threadIdx.x;
    int scq = tid >> 5;
    int lane = tid & 31;
    int cpl = lane >> 2;
    int j = lane & 3;
    int scb = scq * 4;

    u64t acc[2][9];
#pragma unroll
    for (int i = 0; i < 2; i++)
#pragma unroll
        for (int k = 0; k < 9; k++) acc[i][k] = 0ull;

    const float* xb = x + (size_t)(b * CH + cgrp * 8) * HWSZ;
    const float* spb = g_space + (size_t)b * 16 * HWSZ;

    load_x_dup(s_x, xb, r0 - 1, tid);
    load_x_dup(s_x, xb, r0, tid);

    const int xoff = cpl * XCP + j * XCHUNK;
    const int spoff = 866 * j + scb;

    int sc_c = tid >> 3;
    int t8 = tid & 7;
    const float* sp_src0 = spb + sc_c * HWSZ + t8;
    float* sp_dst = s_spT + t8 * 18 + sc_c;

    for (int r = r0; r < r0 + RPS; r++) {
        __syncthreads();
        load_x_dup(s_x, xb, r + 1, tid);
        {
            const float* srow = sp_src0 + r * WW;
#pragma unroll
            for (int m = 0; m < 24; m++) {
                sp_dst[144 * m + 2 * (m / 6)] = srow[8 * m];
            }
        }
        __syncthreads();

        int sm1 = (r + 2) % 3;
        int sm0 = r % 3;
        int sp1 = (r + 1) % 3;
        const float* xr0 = s_x + xoff + sm1 * XSLOT;
        const float* xr1 = s_x + xoff + sm0 * XSLOT;
        const float* xr2 = s_x + xoff + sp1 * XSLOT;

        u64t m0 = *(const u64t*)(xr0);
        u64t m1 = *(const u64t*)(xr1);
        u64t m2 = *(const u64t*)(xr2);
        u64t c0 = *(const u64t*)(xr0 + 2);
        u64t c1 = *(const u64t*)(xr1 + 2);
        u64t c2 = *(const u64t*)(xr2 + 2);
        const float* snp = s_spT + spoff;

#pragma unroll 4
        for (int cc = 0; cc < 48; cc++) {
            u64t p0 = *(const u64t*)(xr0 + 2 * (cc + 2));
            u64t p1 = *(const u64t*)(xr1 + 2 * (cc + 2));
            u64t p2 = *(const u64t*)(xr2 + 2 * (cc + 2));
            u64t snA = *(const u64t*)(snp);
            u64t snB = *(const u64t*)(snp + 2);

            acc[0][0] = ffma2(snA, m0, acc[0][0]);
            acc[0][1] = ffma2(snA, c0, acc[0][1]);
            acc[0][2] = ffma2(snA, p0, acc[0][2]);
            acc[0][3] = ffma2(snA, m1, acc[0][3]);
            acc[0][4] = ffma2(snA, c1, acc[0][4]);
            acc[0][5] = ffma2(snA, p1, acc[0][5]);
            acc[0][6] = ffma2(snA, m2, acc[0][6]);
            acc[0][7] = ffma2(snA, c2, acc[0][7]);
            acc[0][8] = ffma2(snA, p2, acc[0][8]);

            acc[1][0] = ffma2(snB, m0, acc[1][0]);
            acc[1][1] = ffma2(snB, c0, acc[1][1]);
            acc[1][2] = ffma2(snB, p0, acc[1][2]);
            acc[1][3] = ffma2(snB, m1, acc[1][3]);
            acc[1][4] = ffma2(snB, c1, acc[1][4]);
            acc[1][5] = ffma2(snB, p1, acc[1][5]);
            acc[1][6] = ffma2(snB, m2, acc[1][6]);
            acc[1][7] = ffma2(snB, c2, acc[1][7]);
            acc[1][8] = ffma2(snB, p2, acc[1][8]);

            m0 = c0; c0 = p0;
            m1 = c1; c1 = p1;
            m2 = c2; c2 = p2;
            snp += SPCOLSTRIDE;
        }
    }

    int cp = cgrp * 8 + cpl;
#pragma unroll
    for (int scp = 0; scp < 2; scp++) {
        int sc0 = scb + scp * 2;
        int sc1 = sc0 + 1;
        int sA = sc0 & 7, cA = sc0 >> 3;
        int sB = sc1 & 7, cB = sc1 >> 3;
        float* dA = &g_P[(((b * 8 + sA) * 2 + cA) * 64 + cp) * 9];
        float* dB = &g_P[(((b * 8 + sB) * 2 + cB) * 64 + cp) * 9];
#pragma unroll
        for (int k = 0; k < 9; k++) {
            float2 v = unpack2(acc[scp][k]);
            atomicAdd(&dA[k], v.x);
            atomicAdd(&dB[k], v.y);
        }
    }
}

// ---------------- kernel 3a: tok[b][c][d] ----------------
__global__ __launch_bounds__(256) void k_tok(const float* __restrict__ Wx,
                                             const float* __restrict__ Wcs) {
    __shared__ float s_part[4][64];
    int s = blockIdx.x, c = blockIdx.y, b = blockIdx.z;
    int tid = threadIdx.x;
    int d = tid & 63;
    int q = tid >> 6;            // 0..3

    const float4* row = (const float4*)(Wx + (s * CH + d) * 576) + q * 36;
    const float4* pp = (const float4*)(g_P + (((b * NSP + s) * NCLS + c) * CH) * 9) + q * 36;
    float dot = 0.f;
#pragma unroll
    for (int m = 0; m < 36; m++) {
        float4 wv = row[m];
        float4 pv = pp[m];
        dot += wv.x * pv.x + wv.y * pv.y + wv.z * pv.z + wv.w * pv.w;
    }
    s_part[q][d] = dot;
    __syncthreads();
    if (tid < 64) {
        float inv = Wcs[s] / g_S[(b * NCLS + c) * NSP + s];
        float t = s_part[0][tid] + s_part[1][tid] + s_part[2][tid] + s_part[3][tid];
        atomicAdd(&g_tok[(b * NCLS + c) * CH + tid], inv * t);
    }
}

// ---------------- kernel 3b: U[b][c][k][o] ----------------
__global__ __launch_bounds__(576) void k_U() {
    __shared__ float s_tok[64];
    int c = blockIdx.x, b = blockIdx.y;
    int tid = threadIdx.x;
    if (tid < 64) s_tok[tid] = g_tok[(b * NCLS + c) * CH + tid];
    __syncthreads();
    int k = tid >> 6;            // 0..8
    int o = tid & 63;
    float a = 0.f;
#pragma unroll 16
    for (int dd = 0; dd < 64; dd++)
        a += g_wT[dd * 576 + k * 64 + o] * s_tok[dd];
    g_U[((b * 2 + c) * 9 + k) * 64 + o] = a;
}

// ---------------- f32x2 tile conv: warp = row, lane = (oq, ph) ----------------
// Output pixels: (row, ph*8 + 2*j2 + lane-in-pair), 4 o per thread.
__device__ __forceinline__ void conv_tile2(const float s_g[2][10][20],
                                           const float s_U[2][9][64],
                                           int row, int o0, int ph, u64t acc2[4][4]) {
#pragma unroll
    for (int oo = 0; oo < 4; oo++)
#pragma unroll
        for (int j = 0; j < 4; j++) acc2[oo][j] = 0ull;
#pragma unroll
    for (int c = 0; c < 2; c++) {
#pragma unroll
        for (int ky = 0; ky < 3; ky++) {
            const float* vrow = &s_g[c][row + ky][ph * 8];
            u64t v2[5];
#pragma unroll
            for (int i2 = 0; i2 < 5; i2++) v2[i2] = *(const u64t*)(vrow + 2 * i2);
            u64t w1[4];
#pragma unroll
            for (int j = 0; j < 4; j++) w1[j] = shl_pair(v2[j], v2[j + 1]);
#pragma unroll
            for (int kx = 0; kx < 3; kx++) {
                float4 uv = *(const float4*)&s_U[c][ky * 3 + kx][o0];
                u64t u0 = pack1(uv.x), u1 = pack1(uv.y);
                u64t u2 = pack1(uv.z), u3 = pack1(uv.w);
#pragma unroll
                for (int j = 0; j < 4; j++) {
                    u64t sel = (kx == 0) ? v2[j] : (kx == 1) ? w1[j] : v2[j + 1];
                    acc2[0][j] = ffma2(sel, u0, acc2[0][j]);
                    acc2[1][j] = ffma2(sel, u1, acc2[1][j]);
                    acc2[2][j] = ffma2(sel, u2, acc2[2][j]);
                    acc2[3][j] = ffma2(sel, u3, acc2[3][j]);
                }
            }
        }
    }
}

__device__ __forceinline__ void load_gU_tiles(float s_g[2][10][20], float s_U[2][9][64],
                                              int b, int th0, int tw0, int tid) {
    {
        float4* dst = (float4*)s_U;
        const float4* src = (const float4*)(g_U + b * 1152);
        for (int i = tid; i < 288; i += 256) dst[i] = src[i];
    }
    if (tid < 180) {
        int r = tid / 18, c2 = tid % 18;
        int gh = th0 + r - 1, gw = tw0 + c2 - 1;
        float v0 = 0.f, v1 = 0.f;
        if (gh >= 0 && gh < HH && gw >= 0 && gw < WW) {
            v0 = g_g[(b * NCLS + 0) * HWSZ + gh * WW + gw];
            v1 = g_g[(b * NCLS + 1) * HWSZ + gh * WW + gw];
        }
        s_g[0][r][c2] = v0;
        s_g[1][r][c2] = v1;
    }
}

// ---------------- kernel 4: BN statistics pass ----------------
__global__ __launch_bounds__(256) void k_bnstats() {
    __shared__ __align__(16) float s_g[2][10][20];
    __shared__ __align__(16) float s_U[2][9][64];
    __shared__ float s_red[2][8][64];
    int b = blockIdx.z;
    int th0 = blockIdx.y * 8, tw0 = blockIdx.x * 16;
    int tid = threadIdx.x;
    load_gU_tiles(s_g, s_U, b, th0, tw0, tid);
    __syncthreads();

    int row = tid >> 5, lane = tid & 31;
    int oq = lane >> 1, ph = lane & 1;
    int o0 = oq * 4;

    u64t acc2[4][4];
    conv_tile2(s_g, s_U, row, o0, ph, acc2);

#pragma unroll
    for (int oo = 0; oo < 4; oo++) {
        float ss = 0.f, s2 = 0.f;
#pragma unroll
        for (int j = 0; j < 4; j++) {
            float2 v = unpack2(acc2[oo][j]);
            ss += v.x + v.y;
            s2 += v.x * v.x + v.y * v.y;
        }
        ss += __shfl_xor_sync(0xffffffffu, ss, 1);
        s2 += __shfl_xor_sync(0xffffffffu, s2, 1);
        if (ph == 0) {
            s_red[0][row][o0 + oo] = ss;
            s_red[1][row][o0 + oo] = s2;
        }
    }
    __syncthreads();
    if (tid < 64) {
        float ts = 0.f, t2 = 0.f;
#pragma unroll
        for (int w = 0; w < 8; w++) {
            ts += s_red[0][w][tid];
            t2 += s_red[1][w][tid];
        }
        atomicAdd(&g_bnsum[tid], ts);
        atomicAdd(&g_bnsq[tid], t2);
    }
}

// ---------------- kernel 5: recompute conv, fuse BNfin+BN+ReLU+residual ----------------
__global__ __launch_bounds__(256) void k_final(const float* __restrict__ x,
                                               const float* __restrict__ gamma,
                                               const float* __restrict__ beta,
                                               float* __restrict__ out) {
    __shared__ __align__(16) float s_g[2][10][20];
    __shared__ __align__(16) float s_U[2][9][64];
    __shared__ float s_a[64], s_b[64];
    int b = blockIdx.z;
    int th0 = blockIdx.y * 8, tw0 = blockIdx.x * 16;
    int tid = threadIdx.x;
    load_gU_tiles(s_g, s_U, b, th0, tw0, tid);
    if (tid >= 192 && tid < 256) {
        int o = tid - 192;
        const float nInv = 1.0f / (float)(BB * HWSZ);
        float mean = g_bnsum[o] * nInv;
        float var = g_bnsq[o] * nInv - mean * mean;
        float a = gamma[o] * rsqrtf(var + 1e-5f);
        s_a[o] = a;
        s_b[o] = beta[o] - mean * a;
    }
    __syncthreads();

    int row = tid >> 5, lane = tid & 31;
    int oq = lane >> 1, ph = lane & 1;
    int o0 = oq * 4;

    u64t acc2[4][4];
    conv_tile2(s_g, s_U, row, o0, ph, acc2);

#pragma unroll
    for (int oo = 0; oo < 4; oo++) {
        int o = o0 + oo;
        float a = s_a[o], bb = s_b[o];
        size_t off = (((size_t)b * CH + o) * HH + th0 + row) * WW + tw0 + ph * 8;
        float2 t0 = unpack2(acc2[oo][0]);
        float2 t1 = unpack2(acc2[oo][1]);
        float2 t2 = unpack2(acc2[oo][2]);
        float2 t3 = unpack2(acc2[oo][3]);
        const float4 xlo = *(const float4*)(x + off);
        const float4 xhi = *(const float4*)(x + off + 4);
        float4 rlo, rhi;
        rlo.x = xlo.x + fmaxf(t0.x * a + bb, 0.f);
        rlo.y = xlo.y + fmaxf(t0.y * a + bb, 0.f);
        rlo.z = xlo.z + fmaxf(t1.x * a + bb, 0.f);
        rlo.w = xlo.w + fmaxf(t1.y * a + bb, 0.f);
        rhi.x = xhi.x + fmaxf(t2.x * a + bb, 0.f);
        rhi.y = xhi.y + fmaxf(t2.y * a + bb, 0.f);
        rhi.z = xhi.z + fmaxf(t3.x * a + bb, 0.f);
        rhi.w = xhi.w + fmaxf(t3.y * a + bb, 0.f);
        *(float4*)(out + off) = rlo;
        *(float4*)(out + off + 4) = rhi;
    }
}

// ---------------- launch ----------------
extern "C" void kernel_launch(void* const* d_in, const int* in_sizes, int n_in,
                              void* d_out, int out_size) {
    const float* x      = (const float*)d_in[0];
    const float* cs     = (const float*)d_in[1];
    const float* Wcsp   = (const float*)d_in[2];
    const float* Wx     = (const float*)d_in[3];
    const float* Wcs    = (const float*)d_in[4];
    const float* Wcv    = (const float*)d_in[5];
    const float* Wa     = (const float*)d_in[6];
    const float* Wcomb  = (const float*)d_in[7];
    const float* Wsing  = (const float*)d_in[8];
    const float* gamma  = (const float*)d_in[9];
    const float* beta   = (const float*)d_in[10];
    float* out = (float*)d_out;

    k_zero<<<288, 256>>>(Wcv, Wa, Wcomb);
    k_wT<<<144, 256>>>(Wsing);
    k_spaceg<<<dim3(48, 8), 256>>>(cs, Wcsp);
    k_P<<<dim3(32, 8, 8), 128>>>(x);
    k_tok<<<dim3(8, 2, 8), 256>>>(Wx, Wcs);
    k_U<<<dim3(2, 8), 576>>>();
    k_bnstats<<<dim3(12, 24, 8), 256>>>();
    k_final<<<dim3(12, 24, 8), 256>>>(x, gamma, beta, out);
}

// round 17
// speedup vs baseline: 1.1388x; 1.1388x over previous
#include <cuda_runtime.h>
#include <math.h>

// Problem constants
constexpr int BB   = 8;
constexpr int NCLS = 2;
constexpr int NSP  = 8;
constexpr int CH   = 64;
constexpr int HH   = 192;
constexpr int WW   = 192;
constexpr int HWSZ = HH * WW;   // 36864
constexpr int RPS  = 12;        // rows per strip in k_P (16 strips — best measured)

// k_P smem layout constants (x stored as duplicated f32x2 pairs)
constexpr int XCHUNK = 102;
constexpr int XSLOT  = 4 * XCHUNK;         // 408
constexpr int XCP    = 3 * XSLOT;          // 1224
constexpr int SPCOLSTRIDE = 18;
constexpr int SPSZ = 3464;

constexpr int LUTN = 512;

typedef unsigned long long u64t;

// ---------------- device scratch ----------------
__device__ float g_space[BB * NCLS * NSP * HWSZ];   // [b][sc][hw]
__device__ float g_S[BB * NCLS * NSP];
__device__ float g_P[BB * NSP * NCLS * CH * 9];     // [b][s][c][c'][k]
__device__ float g_tok[BB * NCLS * CH];             // [b][c][d]
__device__ float g_wT[CH * CH * 9];                 // [d][k][o]
__device__ float g_U[BB * NCLS * 9 * CH];           // [b][c][k][o]
__device__ float g_g[BB * NCLS * HWSZ];             // [b][c][hw]
__device__ float g_lut[LUTN + 2];                   // g(cp) lookup
__device__ float g_bnsum[CH];
__device__ float g_bnsq[CH];

__device__ __forceinline__ float sigmoidf_(float x) {
    return 1.0f / (1.0f + __expf(-x));
}

// ---- packed f32x2 helpers ----
__device__ __forceinline__ u64t pack1(float v) {
    u64t r; asm("mov.b64 %0, {%1, %1};" : "=l"(r) : "f"(v)); return r;
}
__device__ __forceinline__ u64t ffma2(u64t a, u64t b, u64t c) {
    u64t d; asm("fma.rn.f32x2 %0, %1, %2, %3;" : "=l"(d) : "l"(a), "l"(b), "l"(c)); return d;
}
__device__ __forceinline__ float2 unpack2(u64t v) {
    float2 f; asm("mov.b64 {%0, %1}, %2;" : "=f"(f.x), "=f"(f.y) : "l"(v)); return f;
}
// (hi(a), lo(b)) -> new pair
__device__ __forceinline__ u64t shl_pair(u64t a, u64t b) {
    float2 fa = unpack2(a), fb = unpack2(b);
    u64t r; asm("mov.b64 %0, {%1, %2};" : "=l"(r) : "f"(fa.y), "f"(fb.x));
    return r;
}

// ---------------- kernel 0a: zero accumulators + build g-LUT ----------------
__global__ void k_zero(const float* __restrict__ Wcv,
                       const float* __restrict__ Wa,
                       const float* __restrict__ Wcomb) {
    int i = blockIdx.x * blockDim.x + threadIdx.x;
    if (i < BB * NSP * NCLS * CH * 9) g_P[i] = 0.f;
    if (i < CH) { g_bnsum[i] = 0.f; g_bnsq[i] = 0.f; }
    if (i < BB * NCLS * NSP) g_S[i] = 0.f;
    if (i < BB * NCLS * CH) g_tok[i] = 0.f;
    if (i < LUTN + 2) {
        float t = fminf((float)i / (float)LUTN, 1.0f);
        float acc = 0.f;
#pragma unroll
        for (int s = 0; s < 8; s++)
            acc += Wcomb[s] * Wcv[s] * sigmoidf_(Wa[s] * t);
        g_lut[i] = acc;
    }
}

// ---------------- kernel 0b: transpose W_single (OIHW -> [d][k][o]) ----------------
__global__ void k_wT(const float* __restrict__ Ws) {
    int i = blockIdx.x * blockDim.x + threadIdx.x;
    if (i < CH * CH * 9) {
        int o = i / 576;
        int rem = i % 576;
        int d = rem / 9;
        int k = rem % 9;
        g_wT[d * 576 + k * 64 + o] = Ws[i];
    }
}

// ---------------- kernel 1: space channels + sums + g maps (LUT for g) ----------------
// grid (48, 8): 4-row tiles. block 256, 3 pixels/thread.
__global__ __launch_bounds__(256) void k_spaceg(const float* __restrict__ cs,
                                                const float* __restrict__ Wcsp) {
    __shared__ float s_sig[2][6][194];   // sigmoid(cs) tile with halo
    __shared__ float s_lut[LUTN + 2];
    int tid = threadIdx.x;
    int b = blockIdx.y;
    int r0 = blockIdx.x * 4;

    for (int i = tid; i < LUTN + 2; i += 256) s_lut[i] = g_lut[i];

    // load sigmoid tile: 2 classes x 6 rows x 194 cols
    for (int i = tid; i < 2 * 6 * 194; i += 256) {
        int c = i / 1164;
        int rem = i - c * 1164;
        int rr = rem / 194;
        int cc = rem - rr * 194;
        int gh = r0 + rr - 1, gw = cc - 1;
        float v = 0.f;
        if (gh >= 0 && gh < HH && gw >= 0 && gw < WW)
            v = sigmoidf_(cs[(b * NCLS + c) * HWSZ + gh * WW + gw]);
        s_sig[c][rr][cc] = v;
    }
    __syncthreads();

    float sums[2 * NSP];
#pragma unroll
    for (int i = 0; i < 16; i++) sums[i] = 0.f;

#pragma unroll
    for (int pi = 0; pi < 3; pi++) {
        int pl = tid + pi * 256;           // 0..767
        int lr = pl / WW, w = pl - lr * WW;
        int p = (r0 + lr) * WW + w;
#pragma unroll
        for (int c = 0; c < 2; c++) {
            float n[9];
#pragma unroll
            for (int dy = 0; dy < 3; dy++)
#pragma unroll
                for (int dx = 0; dx < 3; dx++)
                    n[dy * 3 + dx] = s_sig[c][lr + dy][w + dx];

            float ch0 = n[4];
            g_space[((b * NCLS + c) * NSP + 0) * HWSZ + p] = ch0;
            sums[c * NSP] += ch0;
#pragma unroll
            for (int j = 0; j < 7; j++) {
                float z = 0.f;
#pragma unroll
                for (int k = 0; k < 9; k++) z += Wcsp[j * 9 + k] * n[k];
                float v = sigmoidf_(z);
                g_space[((b * NCLS + c) * NSP + j + 1) * HWSZ + p] = v;
                sums[c * NSP + j + 1] += v;
            }
            // g via LUT lerp
            float f = ch0 * (float)LUTN;
            int idx = (int)f;
            float fr = f - (float)idx;
            float l0 = s_lut[idx];
            g_g[(b * NCLS + c) * HWSZ + p] = l0 + fr * (s_lut[idx + 1] - l0);
        }
    }

#pragma unroll
    for (int sc = 0; sc < 16; sc++) {
        float v = sums[sc];
#pragma unroll
        for (int off = 16; off; off >>= 1)
            v += __shfl_down_sync(0xffffffffu, v, off);
        if ((tid & 31) == 0) {
            int c = sc / NSP, s = sc % NSP;
            atomicAdd(&g_S[(b * NCLS + c) * NSP + s], v);
        }
    }
}

// ---------------- kernel 2: P correlation (dup-x f32x2, conflict-free) ----------------
__device__ __forceinline__ void load_x_dup(float* s_x, const float* __restrict__ xb,
                                           int grow, int tid) {
    int slot = ((grow % 3) + 3) % 3;
    bool rok = (grow >= 0 && grow < HH);
    const float* rowp = xb + grow * WW;
#pragma unroll
    for (int m = 0; m < 13; m++) {
        int i = tid + m * 128;
        if (i < 1600) {
            int cp = i / 200;
            int rem = i - cp * 200;
            int j = rem / 50;
            int t = rem - j * 50;
            int col = 48 * j - 1 + t;
            float v = 0.f;
            if (rok && col >= 0 && col < WW) v = rowp[cp * HWSZ + col];
            *(u64t*)(s_x + cp * XCP + slot * XSLOT + j * XCHUNK + 2 * t) = pack1(v);
        }
    }
}

__global__ __launch_bounds__(128) void k_P(const float* __restrict__ x) {
    __shared__ __align__(16) float s_x[8 * XCP];      // 39.2 KB
    __shared__ __align__(16) float s_spT[SPSZ];       // 13.9 KB

    int b = blockIdx.z, cgrp = blockIdx.y, strip = blockIdx.x;
    int r0 = strip * RPS;
    int tid = threadIdx.x;
    int scq = tid >> 5;
    int lane = tid & 31;
    int cpl = lane >> 2;
    int j = lane & 3;
    int scb = scq * 4;

    u64t acc[2][9];
#pragma unroll
    for (int i = 0; i < 2; i++)
#pragma unroll
        for (int k = 0; k < 9; k++) acc[i][k] = 0ull;

    const float* xb = x + (size_t)(b * CH + cgrp * 8) * HWSZ;
    const float* spb = g_space + (size_t)b * 16 * HWSZ;

    load_x_dup(s_x, xb, r0 - 1, tid);
    load_x_dup(s_x, xb, r0, tid);

    const int xoff = cpl * XCP + j * XCHUNK;
    const int spoff = 866 * j + scb;

    int sc_c = tid >> 3;
    int t8 = tid & 7;
    const float* sp_src0 = spb + sc_c * HWSZ + t8;
    float* sp_dst = s_spT + t8 * 18 + sc_c;

    for (int r = r0; r < r0 + RPS; r++) {
        __syncthreads();
        load_x_dup(s_x, xb, r + 1, tid);
        {
            const float* srow = sp_src0 + r * WW;
#pragma unroll
            for (int m = 0; m < 24; m++) {
                sp_dst[144 * m + 2 * (m / 6)] = srow[8 * m];
            }
        }
        __syncthreads();

        int sm1 = (r + 2) % 3;
        int sm0 = r % 3;
        int sp1 = (r + 1) % 3;
        const float* xr0 = s_x + xoff + sm1 * XSLOT;
        const float* xr1 = s_x + xoff + sm0 * XSLOT;
        const float* xr2 = s_x + xoff + sp1 * XSLOT;

        u64t m0 = *(const u64t*)(xr0);
        u64t m1 = *(const u64t*)(xr1);
        u64t m2 = *(const u64t*)(xr2);
        u64t c0 = *(const u64t*)(xr0 + 2);
        u64t c1 = *(const u64t*)(xr1 + 2);
        u64t c2 = *(const u64t*)(xr2 + 2);
        const float* snp = s_spT + spoff;

#pragma unroll 4
        for (int cc = 0; cc < 48; cc++) {
            u64t p0 = *(const u64t*)(xr0 + 2 * (cc + 2));
            u64t p1 = *(const u64t*)(xr1 + 2 * (cc + 2));
            u64t p2 = *(const u64t*)(xr2 + 2 * (cc + 2));
            u64t snA = *(const u64t*)(snp);
            u64t snB = *(const u64t*)(snp + 2);

            acc[0][0] = ffma2(snA, m0, acc[0][0]);
            acc[0][1] = ffma2(snA, c0, acc[0][1]);
            acc[0][2] = ffma2(snA, p0, acc[0][2]);
            acc[0][3] = ffma2(snA, m1, acc[0][3]);
            acc[0][4] = ffma2(snA, c1, acc[0][4]);
            acc[0][5] = ffma2(snA, p1, acc[0][5]);
            acc[0][6] = ffma2(snA, m2, acc[0][6]);
            acc[0][7] = ffma2(snA, c2, acc[0][7]);
            acc[0][8] = ffma2(snA, p2, acc[0][8]);

            acc[1][0] = ffma2(snB, m0, acc[1][0]);
            acc[1][1] = ffma2(snB, c0, acc[1][1]);
            acc[1][2] = ffma2(snB, p0, acc[1][2]);
            acc[1][3] = ffma2(snB, m1, acc[1][3]);
            acc[1][4] = ffma2(snB, c1, acc[1][4]);
            acc[1][5] = ffma2(snB, p1, acc[1][5]);
            acc[1][6] = ffma2(snB, m2, acc[1][6]);
            acc[1][7] = ffma2(snB, c2, acc[1][7]);
            acc[1][8] = ffma2(snB, p2, acc[1][8]);

            m0 = c0; c0 = p0;
            m1 = c1; c1 = p1;
            m2 = c2; c2 = p2;
            snp += SPCOLSTRIDE;
        }
    }

    int cp = cgrp * 8 + cpl;
#pragma unroll
    for (int scp = 0; scp < 2; scp++) {
        int sc0 = scb + scp * 2;
        int sc1 = sc0 + 1;
        int sA = sc0 & 7, cA = sc0 >> 3;
        int sB = sc1 & 7, cB = sc1 >> 3;
        float* dA = &g_P[(((b * 8 + sA) * 2 + cA) * 64 + cp) * 9];
        float* dB = &g_P[(((b * 8 + sB) * 2 + cB) * 64 + cp) * 9];
#pragma unroll
        for (int k = 0; k < 9; k++) {
            float2 v = unpack2(acc[scp][k]);
            atomicAdd(&dA[k], v.x);
            atomicAdd(&dB[k], v.y);
        }
    }
}

// ---------------- kernel 3a: tok[b][c][d] ----------------
__global__ __launch_bounds__(256) void k_tok(const float* __restrict__ Wx,
                                             const float* __restrict__ Wcs) {
    __shared__ float s_part[4][64];
    int s = blockIdx.x, c = blockIdx.y, b = blockIdx.z;
    int tid = threadIdx.x;
    int d = tid & 63;
    int q = tid >> 6;            // 0..3

    const float4* row = (const float4*)(Wx + (s * CH + d) * 576) + q * 36;
    const float4* pp = (const float4*)(g_P + (((b * NSP + s) * NCLS + c) * CH) * 9) + q * 36;
    float dot = 0.f;
#pragma unroll
    for (int m = 0; m < 36; m++) {
        float4 wv = row[m];
        float4 pv = pp[m];
        dot += wv.x * pv.x + wv.y * pv.y + wv.z * pv.z + wv.w * pv.w;
    }
    s_part[q][d] = dot;
    __syncthreads();
    if (tid < 64) {
        float inv = Wcs[s] / g_S[(b * NCLS + c) * NSP + s];
        float t = s_part[0][tid] + s_part[1][tid] + s_part[2][tid] + s_part[3][tid];
        atomicAdd(&g_tok[(b * NCLS + c) * CH + tid], inv * t);
    }
}

// ---------------- kernel 3b: U[b][c][k][o] ----------------
__global__ __launch_bounds__(576) void k_U() {
    __shared__ float s_tok[64];
    int c = blockIdx.x, b = blockIdx.y;
    int tid = threadIdx.x;
    if (tid < 64) s_tok[tid] = g_tok[(b * NCLS + c) * CH + tid];
    __syncthreads();
    int k = tid >> 6;            // 0..8
    int o = tid & 63;
    float a = 0.f;
#pragma unroll 16
    for (int dd = 0; dd < 64; dd++)
        a += g_wT[dd * 576 + k * 64 + o] * s_tok[dd];
    g_U[((b * 2 + c) * 9 + k) * 64 + o] = a;
}

// ---------------- f32x2 tile conv: warp = row, lane = (oq, ph) ----------------
__device__ __forceinline__ void conv_tile2(const float s_g[2][10][20],
                                           const float s_U[2][9][64],
                                           int row, int o0, int ph, u64t acc2[4][4]) {
#pragma unroll
    for (int oo = 0; oo < 4; oo++)
#pragma unroll
        for (int j = 0; j < 4; j++) acc2[oo][j] = 0ull;
#pragma unroll
    for (int c = 0; c < 2; c++) {
#pragma unroll
        for (int ky = 0; ky < 3; ky++) {
            const float* vrow = &s_g[c][row + ky][ph * 8];
            u64t v2[5];
#pragma unroll
            for (int i2 = 0; i2 < 5; i2++) v2[i2] = *(const u64t*)(vrow + 2 * i2);
            u64t w1[4];
#pragma unroll
            for (int j = 0; j < 4; j++) w1[j] = shl_pair(v2[j], v2[j + 1]);
#pragma unroll
            for (int kx = 0; kx < 3; kx++) {
                float4 uv = *(const float4*)&s_U[c][ky * 3 + kx][o0];
                u64t u0 = pack1(uv.x), u1 = pack1(uv.y);
                u64t u2 = pack1(uv.z), u3 = pack1(uv.w);
#pragma unroll
                for (int j = 0; j < 4; j++) {
                    u64t sel = (kx == 0) ? v2[j] : (kx == 1) ? w1[j] : v2[j + 1];
                    acc2[0][j] = ffma2(sel, u0, acc2[0][j]);
                    acc2[1][j] = ffma2(sel, u1, acc2[1][j]);
                    acc2[2][j] = ffma2(sel, u2, acc2[2][j]);
                    acc2[3][j] = ffma2(sel, u3, acc2[3][j]);
                }
            }
        }
    }
}

__device__ __forceinline__ void load_gU_tiles(float s_g[2][10][20], float s_U[2][9][64],
                                              int b, int th0, int tw0, int tid) {
    {
        float4* dst = (float4*)s_U;
        const float4* src = (const float4*)(g_U + b * 1152);
        for (int i = tid; i < 288; i += 256) dst[i] = src[i];
    }
    if (tid < 180) {
        int r = tid / 18, c2 = tid % 18;
        int gh = th0 + r - 1, gw = tw0 + c2 - 1;
        float v0 = 0.f, v1 = 0.f;
        if (gh >= 0 && gh < HH && gw >= 0 && gw < WW) {
            v0 = g_g[(b * NCLS + 0) * HWSZ + gh * WW + gw];
            v1 = g_g[(b * NCLS + 1) * HWSZ + gh * WW + gw];
        }
        s_g[0][r][c2] = v0;
        s_g[1][r][c2] = v1;
    }
}

// ---------------- kernel 4: BN statistics pass ----------------
__global__ __launch_bounds__(256) void k_bnstats() {
    __shared__ __align__(16) float s_g[2][10][20];
    __shared__ __align__(16) float s_U[2][9][64];
    __shared__ float s_red[2][8][64];
    int b = blockIdx.z;
    int th0 = blockIdx.y * 8, tw0 = blockIdx.x * 16;
    int tid = threadIdx.x;
    load_gU_tiles(s_g, s_U, b, th0, tw0, tid);
    __syncthreads();

    int row = tid >> 5, lane = tid & 31;
    int oq = lane >> 1, ph = lane & 1;
    int o0 = oq * 4;

    u64t acc2[4][4];
    conv_tile2(s_g, s_U, row, o0, ph, acc2);

#pragma unroll
    for (int oo = 0; oo < 4; oo++) {
        float ss = 0.f, s2 = 0.f;
#pragma unroll
        for (int j = 0; j < 4; j++) {
            float2 v = unpack2(acc2[oo][j]);
            ss += v.x + v.y;
            s2 += v.x * v.x + v.y * v.y;
        }
        ss += __shfl_xor_sync(0xffffffffu, ss, 1);
        s2 += __shfl_xor_sync(0xffffffffu, s2, 1);
        if (ph == 0) {
            s_red[0][row][o0 + oo] = ss;
            s_red[1][row][o0 + oo] = s2;
        }
    }
    __syncthreads();
    if (tid < 64) {
        float ts = 0.f, t2 = 0.f;
#pragma unroll
        for (int w = 0; w < 8; w++) {
            ts += s_red[0][w][tid];
            t2 += s_red[1][w][tid];
        }
        atomicAdd(&g_bnsum[tid], ts);
        atomicAdd(&g_bnsq[tid], t2);
    }
}

// ---------------- kernel 5: recompute conv, fuse BNfin+BN+ReLU+residual ----------------
__global__ __launch_bounds__(256) void k_final(const float* __restrict__ x,
                                               const float* __restrict__ gamma,
                                               const float* __restrict__ beta,
                                               float* __restrict__ out) {
    __shared__ __align__(16) float s_g[2][10][20];
    __shared__ __align__(16) float s_U[2][9][64];
    __shared__ float s_a[64], s_b[64];
    int b = blockIdx.z;
    int th0 = blockIdx.y * 8, tw0 = blockIdx.x * 16;
    int tid = threadIdx.x;
    load_gU_tiles(s_g, s_U, b, th0, tw0, tid);
    if (tid >= 192 && tid < 256) {
        int o = tid - 192;
        const float nInv = 1.0f / (float)(BB * HWSZ);
        float mean = g_bnsum[o] * nInv;
        float var = g_bnsq[o] * nInv - mean * mean;
        float a = gamma[o] * rsqrtf(var + 1e-5f);
        s_a[o] = a;
        s_b[o] = beta[o] - mean * a;
    }
    __syncthreads();

    int row = tid >> 5, lane = tid & 31;
    int oq = lane >> 1, ph = lane & 1;
    int o0 = oq * 4;

    u64t acc2[4][4];
    conv_tile2(s_g, s_U, row, o0, ph, acc2);

#pragma unroll
    for (int oo = 0; oo < 4; oo++) {
        int o = o0 + oo;
        float a = s_a[o], bb = s_b[o];
        size_t off = (((size_t)b * CH + o) * HH + th0 + row) * WW + tw0 + ph * 8;
        float2 t0 = unpack2(acc2[oo][0]);
        float2 t1 = unpack2(acc2[oo][1]);
        float2 t2 = unpack2(acc2[oo][2]);
        float2 t3 = unpack2(acc2[oo][3]);
        const float4 xlo = *(const float4*)(x + off);
        const float4 xhi = *(const float4*)(x + off + 4);
        float4 rlo, rhi;
        rlo.x = xlo.x + fmaxf(t0.x * a + bb, 0.f);
        rlo.y = xlo.y + fmaxf(t0.y * a + bb, 0.f);
        rlo.z = xlo.z + fmaxf(t1.x * a + bb, 0.f);
        rlo.w = xlo.w + fmaxf(t1.y * a + bb, 0.f);
        rhi.x = xhi.x + fmaxf(t2.x * a + bb, 0.f);
        rhi.y = xhi.y + fmaxf(t2.y * a + bb, 0.f);
        rhi.z = xhi.z + fmaxf(t3.x * a + bb, 0.f);
        rhi.w = xhi.w + fmaxf(t3.y * a + bb, 0.f);
        *(float4*)(out + off) = rlo;
        *(float4*)(out + off + 4) = rhi;
    }
}

// ---------------- launch ----------------
extern "C" void kernel_launch(void* const* d_in, const int* in_sizes, int n_in,
                              void* d_out, int out_size) {
    const float* x      = (const float*)d_in[0];
    const float* cs     = (const float*)d_in[1];
    const float* Wcsp   = (const float*)d_in[2];
    const float* Wx     = (const float*)d_in[3];
    const float* Wcs    = (const float*)d_in[4];
    const float* Wcv    = (const float*)d_in[5];
    const float* Wa     = (const float*)d_in[6];
    const float* Wcomb  = (const float*)d_in[7];
    const float* Wsing  = (const float*)d_in[8];
    const float* gamma  = (const float*)d_in[9];
    const float* beta   = (const float*)d_in[10];
    float* out = (float*)d_out;

    k_zero<<<288, 256>>>(Wcv, Wa, Wcomb);
    k_wT<<<144, 256>>>(Wsing);
    k_spaceg<<<dim3(48, 8), 256>>>(cs, Wcsp);
    k_P<<<dim3(16, 8, 8), 128>>>(x);
    k_tok<<<dim3(8, 2, 8), 256>>>(Wx, Wcs);
    k_U<<<dim3(2, 8), 576>>>();
    k_bnstats<<<dim3(12, 24, 8), 256>>>();
    k_final<<<dim3(12, 24, 8), 256>>>(x, gamma, beta, out);
}